// round 12
// baseline (speedup 1.0000x reference)
#include <cuda_runtime.h>
#include <cuda_fp16.h>
#include <math.h>
#include <cstdint>

// ---------------------------------------------------------------------------
// RoPE MHA on GB300 (sm_103 family-generic target).
// R12: attention softmax de-MUFU'd: ex2.approx.f16x2 probabilities (packed,
//      feed PV mma directly) + row-sum via ones-MMA (no shfl reduction).
//      Table gen merged into convert kernel.
// ---------------------------------------------------------------------------

namespace {
constexpr int Bn=2, Tn=2048, Hn=16, Dhn=64, Dn=1024, Mn=4096;
constexpr float QSC = 0.125f * 1.44269504088896340736f;   // 1/sqrt(64) * log2(e)
}

__device__ __half g_xh[(size_t)Mn*Dn];
__device__ __half g_Wqh[(size_t)Dn*Dn];
__device__ __half g_Wkh[(size_t)Dn*Dn];
__device__ __half g_Wvh[(size_t)Dn*Dn];
__device__ __half g_Woh[(size_t)Dn*Dn];
__device__ __half g_Qh[(size_t)Mn*Dn];
__device__ __half g_Kh[(size_t)Mn*Dn];
__device__ __half g_Vh[(size_t)Mn*Dn];
__device__ __half g_attn[(size_t)Mn*Dn];
__device__ float2 g_tbl[(size_t)Tn*32];        // (cos, sin) per (t, i)

// ----------------------------- helpers ------------------------------------
__device__ __forceinline__ uint32_t smem_u32(const void* p) {
    uint32_t a;
    asm("{ .reg .u64 t; cvta.to.shared.u64 t, %1; cvt.u32.u64 %0, t; }"
        : "=r"(a) : "l"(p));
    return a;
}
__device__ __forceinline__ uint32_t pkh2(float lo, float hi) {
    __half2 h = __floats2half2_rn(lo, hi);
    return *reinterpret_cast<uint32_t*>(&h);
}
__device__ __forceinline__ float ex2f(float x) {
    float r;
    asm("ex2.approx.f32 %0, %1;" : "=f"(r) : "f"(x));
    return r;
}
__device__ __forceinline__ uint32_t h2ex2(uint32_t x) {   // packed 2^h for half2
    uint32_t r;
    asm("ex2.approx.f16x2 %0, %1;" : "=r"(r) : "r"(x));
    return r;
}
__device__ __forceinline__ void mma16816(float* c, const uint32_t* a,
                                         uint32_t b0, uint32_t b1) {
    asm volatile(
        "mma.sync.aligned.m16n8k16.row.col.f32.f16.f16.f32 "
        "{%0,%1,%2,%3},{%4,%5,%6,%7},{%8,%9},{%0,%1,%2,%3};"
        : "+f"(c[0]), "+f"(c[1]), "+f"(c[2]), "+f"(c[3])
        : "r"(a[0]), "r"(a[1]), "r"(a[2]), "r"(a[3]), "r"(b0), "r"(b1));
}
__device__ __forceinline__ void ldsm4(uint32_t* r, uint32_t addr) {
    asm volatile("ldmatrix.sync.aligned.m8n8.x4.shared.b16 {%0,%1,%2,%3}, [%4];"
        : "=r"(r[0]), "=r"(r[1]), "=r"(r[2]), "=r"(r[3]) : "r"(addr));
}
__device__ __forceinline__ void ldsm4t(uint32_t* r, uint32_t addr) {
    asm volatile("ldmatrix.sync.aligned.m8n8.x4.trans.shared.b16 {%0,%1,%2,%3}, [%4];"
        : "=r"(r[0]), "=r"(r[1]), "=r"(r[2]), "=r"(r[3]) : "r"(addr));
}
#define CP_ASYNC16(dst, src) \
    asm volatile("cp.async.cg.shared.global [%0], [%1], 16;" :: "r"(dst), "l"(src))
#define CP_COMMIT() asm volatile("cp.async.commit_group;" ::: "memory")
#define CP_WAIT(n)  asm volatile("cp.async.wait_group %0;" :: "n"(n) : "memory")

// ---------------------------------------------------------------------------
// Fused fp32->fp16 conversion of x + 4 weights, AND RoPE table (one launch).
// ---------------------------------------------------------------------------
namespace {
constexpr int XN4 = Mn*Dn/4, WN4 = Dn*Dn/4;
constexpr int CVT_TOTAL = XN4 + 4 * WN4;       // 2,097,152
constexpr int TBL_TOTAL = Tn * 32;             // 65,536
}

__global__ void cvt_all_kernel(const float* __restrict__ x,
                               const float* __restrict__ Wq, const float* __restrict__ Wk,
                               const float* __restrict__ Wv, const float* __restrict__ Wo)
{
    const int i = blockIdx.x * blockDim.x + threadIdx.x;
    if (i >= CVT_TOTAL) {
        const int idx = i - CVT_TOTAL;
        if (idx < TBL_TOTAL) {
            const int fi = idx & 31, t = idx >> 5;
            const float invf = 1.0f / powf(10000.0f, (float)fi * (1.0f / 32.0f));
            float sn, cs;
            sincosf((float)t * invf, &sn, &cs);
            g_tbl[idx] = make_float2(cs, sn);
        }
        return;
    }
    const float* src; __half* dst; int off;
    if (i < XN4)            { src = x;  dst = g_xh;  off = i; }
    else {
        const int j = i - XN4, sel = j / WN4; off = j % WN4;
        src = (sel == 0) ? Wq : (sel == 1) ? Wk : (sel == 2) ? Wv : Wo;
        dst = (sel == 0) ? g_Wqh : (sel == 1) ? g_Wkh : (sel == 2) ? g_Wvh : g_Woh;
    }
    const float4 v = ((const float4*)src)[off];
    uint2 o;
    o.x = pkh2(v.x, v.y);
    o.y = pkh2(v.z, v.w);
    ((uint2*)dst)[off] = o;
}

// ===========================================================================
// GEMM mainloop: 128x128 tile, 8 warps as 4m x 2n (32 rows x 64 cols each),
//   3-stage cp.async, K-chunk 64, 144B smem row stride.
// ===========================================================================
namespace {
constexpr int STGB  = 18432;
constexpr int GSMEM = 6 * STGB;
constexpr int NIT   = 16;
}

__device__ __forceinline__ void gload64(uint32_t dst, const __half* src,
                                        int row, int hf, int k0)
{
    const char* s = (const char*)(src + (size_t)row * 1024 + k0 + hf * 32);
    const uint32_t d = dst + row * 144 + hf * 64;
    CP_ASYNC16(d,      s);
    CP_ASYNC16(d + 16, s + 16);
    CP_ASYNC16(d + 32, s + 32);
    CP_ASYNC16(d + 48, s + 48);
}

__device__ __forceinline__ void gemm_mainloop(const __half* Ag, const __half* Wg,
                                              uint32_t ub, float (&acc)[2][8][4])
{
    const int tid  = threadIdx.x;
    const int lane = tid & 31;
    const int wid  = tid >> 5;
    const int lm   = lane & 15;
    const int lh16 = (lane >> 4) << 4;
    const int wm = wid & 3, wn = wid >> 2;
    const int row = tid >> 1, hf = tid & 1;

    #pragma unroll
    for (int i = 0; i < 2; i++)
        #pragma unroll
        for (int j = 0; j < 8; j++)
            #pragma unroll
            for (int e = 0; e < 4; e++) acc[i][j][e] = 0.f;

    gload64(ub,            Ag, row, hf, 0);
    gload64(ub + 3 * STGB, Wg, row, hf, 0);
    CP_COMMIT();
    gload64(ub + STGB,            Ag, row, hf, 64);
    gload64(ub + 3 * STGB + STGB, Wg, row, hf, 64);
    CP_COMMIT();

    for (int i = 0; i < NIT; i++) {
        CP_WAIT(1);
        __syncthreads();
        if (i + 2 < NIT) {
            const int s = (i + 2) % 3;
            gload64(ub + s * STGB,       Ag, row, hf, (i + 2) * 64);
            gload64(ub + (3 + s) * STGB, Wg, row, hf, (i + 2) * 64);
        }
        CP_COMMIT();

        const uint32_t uA = ub + (i % 3) * STGB;
        const uint32_t uW = ub + (3 + i % 3) * STGB;
        #pragma unroll
        for (int kb = 0; kb < 4; kb++) {
            uint32_t af[2][4];
            #pragma unroll
            for (int mt = 0; mt < 2; mt++)
                ldsm4(af[mt], uA + (wm*32 + mt*16 + lm) * 144 + kb*32 + lh16);
            uint32_t bf[4][4];
            #pragma unroll
            for (int p = 0; p < 4; p++)
                ldsm4(bf[p], uW + (wn*64 + p*16 + lm) * 144 + kb*32 + lh16);
            #pragma unroll
            for (int mt = 0; mt < 2; mt++)
                #pragma unroll
                for (int nt = 0; nt < 8; nt++) {
                    const int p = nt >> 1, q = nt & 1;
                    mma16816(acc[mt][nt], af[mt], bf[p][q], bf[p][2 + q]);
                }
        }
    }
}

// ===========================================================================
// Fused QKV projection + RoPE epilogue. grid (24, 32): which = bx/8.
// ===========================================================================
__global__ __launch_bounds__(256)
void gemm_qkv_kernel(const float* __restrict__ bq, const float* __restrict__ bk,
                     const float* __restrict__ bv)
{
    extern __shared__ char smc[];
    const uint32_t ub = smem_u32(smc);

    const int which = blockIdx.x >> 3;
    const int n0 = (blockIdx.x & 7) * 128;
    const int m0 = blockIdx.y * 128;

    const __half* Wh = (which == 0) ? g_Wqh : (which == 1) ? g_Wkh : g_Wvh;
    const float* bias = (which == 0) ? bq : (which == 1) ? bk : bv;

    float acc[2][8][4];
    gemm_mainloop(g_xh + (size_t)m0 * 1024, Wh + (size_t)n0 * 1024, ub, acc);

    const int tid = threadIdx.x, lane = tid & 31, wid = tid >> 5;
    const int g = lane >> 2, t = lane & 3;
    const int wm = wid & 3, wn = wid >> 2;

    const int hcol = n0 + wn * 64;       // head-aligned column base
    const int h    = hcol >> 6;

    if (which == 2) {
        #pragma unroll
        for (int mt = 0; mt < 2; mt++) {
            const int r0 = m0 + wm * 32 + mt * 16 + g;
            const int bb = r0 >> 11, tt0 = r0 & (Tn - 1);
            const size_t b0 = ((size_t)(bb * Hn + h) * Tn + tt0) * Dhn;
            const size_t b1 = b0 + 8 * Dhn;
            #pragma unroll
            for (int nt = 0; nt < 8; nt++) {
                const int d = nt * 8 + 2 * t;
                const float2 bv2 = *(const float2*)(bias + hcol + d);
                *(uint32_t*)(g_Vh + b0 + d) = pkh2(acc[mt][nt][0] + bv2.x, acc[mt][nt][1] + bv2.y);
                *(uint32_t*)(g_Vh + b1 + d) = pkh2(acc[mt][nt][2] + bv2.x, acc[mt][nt][3] + bv2.y);
            }
        }
    } else {
        __half* C = (which == 0) ? g_Qh : g_Kh;
        const float sc = (which == 0) ? QSC : 1.0f;
        #pragma unroll
        for (int mt = 0; mt < 2; mt++) {
            const int r0 = m0 + wm * 32 + mt * 16 + g;
            const int bb = r0 >> 11, tt0 = r0 & (Tn - 1), tt1 = tt0 + 8;
            const size_t b0 = ((size_t)(bb * Hn + h) * Tn + tt0) * Dhn;
            const size_t b1 = b0 + 8 * Dhn;
            #pragma unroll
            for (int nt = 0; nt < 4; nt++) {
                const int i0 = nt * 8 + 2 * t;           // d in [0,32)
                const float2 bl = *(const float2*)(bias + hcol + i0);
                const float2 bh = *(const float2*)(bias + hcol + i0 + 32);
                const float4 ca = *(const float4*)(&g_tbl[(size_t)tt0 * 32 + i0]);
                const float4 cb = *(const float4*)(&g_tbl[(size_t)tt1 * 32 + i0]);
                {
                    const float xl0 = acc[mt][nt][0] + bl.x, xl1 = acc[mt][nt][1] + bl.y;
                    const float xh0 = acc[mt][nt+4][0] + bh.x, xh1 = acc[mt][nt+4][1] + bh.y;
                    *(uint32_t*)(C + b0 + i0)      = pkh2((xl0 * ca.x - xh0 * ca.y) * sc,
                                                          (xl1 * ca.z - xh1 * ca.w) * sc);
                    *(uint32_t*)(C + b0 + i0 + 32) = pkh2((xh0 * ca.x + xl0 * ca.y) * sc,
                                                          (xh1 * ca.z + xl1 * ca.w) * sc);
                }
                {
                    const float xl0 = acc[mt][nt][2] + bl.x, xl1 = acc[mt][nt][3] + bl.y;
                    const float xh0 = acc[mt][nt+4][2] + bh.x, xh1 = acc[mt][nt+4][3] + bh.y;
                    *(uint32_t*)(C + b1 + i0)      = pkh2((xl0 * cb.x - xh0 * cb.y) * sc,
                                                          (xl1 * cb.z - xh1 * cb.w) * sc);
                    *(uint32_t*)(C + b1 + i0 + 32) = pkh2((xh0 * cb.x + xl0 * cb.y) * sc,
                                                          (xh1 * cb.z + xl1 * cb.w) * sc);
                }
            }
        }
    }
}

// ===========================================================================
// O projection: out[m,n] = attn[m,:] x Wo[n,:] + bo, fp32 row-major.
// ===========================================================================
__global__ __launch_bounds__(256)
void gemm_o_kernel(const float* __restrict__ bias, float* __restrict__ out)
{
    extern __shared__ char smc[];
    const uint32_t ub = smem_u32(smc);

    const int n0 = blockIdx.x * 128;
    const int m0 = blockIdx.y * 128;

    float acc[2][8][4];
    gemm_mainloop(g_attn + (size_t)m0 * 1024, g_Woh + (size_t)n0 * 1024, ub, acc);

    const int tid = threadIdx.x, lane = tid & 31, wid = tid >> 5;
    const int g = lane >> 2, t = lane & 3;
    const int wm = wid & 3, wn = wid >> 2;

    #pragma unroll
    for (int mt = 0; mt < 2; mt++) {
        const int r0 = m0 + wm * 32 + mt * 16 + g;
        #pragma unroll
        for (int nt = 0; nt < 8; nt++) {
            const int c = n0 + wn * 64 + nt * 8 + 2 * t;
            const float2 bv2 = *(const float2*)(bias + c);
            *(float2*)(out + (size_t)r0 * Dn + c) =
                make_float2(acc[mt][nt][0] + bv2.x, acc[mt][nt][1] + bv2.y);
            *(float2*)(out + (size_t)(r0 + 8) * Dn + c) =
                make_float2(acc[mt][nt][2] + bv2.x, acc[mt][nt][3] + bv2.y);
        }
    }
}

// ===========================================================================
// Flash attention: 128q/CTA, 256 thr, 3-stage cp.async K/V ring,
// exp2-domain softmax with f16x2 MUFU and ones-MMA row sums.
// ===========================================================================
namespace {
constexpr int ATTN_SMEM3 = 18432 + 6 * 9216;
constexpr uint32_t ONESH2 = 0x3C003C00u;       // half2(1.0, 1.0)
}

__global__ __launch_bounds__(256)
void attn_h_kernel(const __half* __restrict__ Q, const __half* __restrict__ K,
                   const __half* __restrict__ V, __half* __restrict__ O)
{
    extern __shared__ char asmc[];
    const uint32_t ub = smem_u32(asmc);

    const int tid  = threadIdx.x;
    const int lane = tid & 31;
    const int wid  = tid >> 5;
    const int g = lane >> 2, t = lane & 3;
    const int lm   = lane & 15;
    const int lh16 = (lane >> 4) << 4;

    const int qt = blockIdx.x, bh = blockIdx.y;
    const int b = bh >> 4, h = bh & 15;

    const char* Qg = (const char*)(Q + (size_t)bh * Tn * 64 + (size_t)qt * 128 * 64);
    const char* Kg = (const char*)(K + (size_t)bh * Tn * 64);
    const char* Vg = (const char*)(V + (size_t)bh * Tn * 64);

    const uint32_t uQ = ub;
    uint32_t uK[3], uV[3];
    #pragma unroll
    for (int s = 0; s < 3; s++) {
        uK[s] = ub + 18432 + s * 9216;
        uV[s] = ub + 18432 + (3 + s) * 9216;
    }

    const int kr = tid >> 2, ko = (tid & 3) * 32;

    // prologue: Q + K/V tiles 0 and 1
    {
        const int qrow = tid >> 1, qhf = tid & 1;
        const uint32_t qd = uQ + qrow * 144 + qhf * 64;
        const char* qs = Qg + qrow * 128 + qhf * 64;
        CP_ASYNC16(qd,      qs);
        CP_ASYNC16(qd + 16, qs + 16);
        CP_ASYNC16(qd + 32, qs + 32);
        CP_ASYNC16(qd + 48, qs + 48);
        CP_ASYNC16(uK[0] + kr * 144 + ko,      Kg + kr * 128 + ko);
        CP_ASYNC16(uK[0] + kr * 144 + ko + 16, Kg + kr * 128 + ko + 16);
        CP_ASYNC16(uV[0] + kr * 144 + ko,      Vg + kr * 128 + ko);
        CP_ASYNC16(uV[0] + kr * 144 + ko + 16, Vg + kr * 128 + ko + 16);
        CP_COMMIT();
        CP_ASYNC16(uK[1] + kr * 144 + ko,      Kg + 8192 + kr * 128 + ko);
        CP_ASYNC16(uK[1] + kr * 144 + ko + 16, Kg + 8192 + kr * 128 + ko + 16);
        CP_ASYNC16(uV[1] + kr * 144 + ko,      Vg + 8192 + kr * 128 + ko);
        CP_ASYNC16(uV[1] + kr * 144 + ko + 16, Vg + 8192 + kr * 128 + ko + 16);
        CP_COMMIT();
    }

    CP_WAIT(1);
    __syncthreads();

    // Q fragments (pre-scaled by 0.125*log2e in the QKV epilogue)
    uint32_t qf[4][4];
    #pragma unroll
    for (int kb = 0; kb < 4; kb++)
        ldsm4(qf[kb], uQ + (wid*16 + lm) * 144 + kb*32 + lh16);

    float ao[8][4];
    #pragma unroll
    for (int d = 0; d < 8; d++)
        #pragma unroll
        for (int e = 0; e < 4; e++) ao[d][e] = 0.f;
    float m0v = -1e30f, m1v = -1e30f, l0 = 0.f, l1 = 0.f;

    for (int i = 0; i < 32; i++) {
        if (i > 0) {
            CP_WAIT(1);
            __syncthreads();
        }
        if (i + 2 < 32) {
            const int s = (i + 2) % 3;
            const char* Kn = Kg + (size_t)(i + 2) * 8192;
            const char* Vn = Vg + (size_t)(i + 2) * 8192;
            CP_ASYNC16(uK[s] + kr * 144 + ko,      Kn + kr * 128 + ko);
            CP_ASYNC16(uK[s] + kr * 144 + ko + 16, Kn + kr * 128 + ko + 16);
            CP_ASYNC16(uV[s] + kr * 144 + ko,      Vn + kr * 128 + ko);
            CP_ASYNC16(uV[s] + kr * 144 + ko + 16, Vn + kr * 128 + ko + 16);
        }
        CP_COMMIT();

        const int s = i % 3;

        // S = Q K^T  (16q x 64k per warp), log2 domain
        float sc[8][4];
        #pragma unroll
        for (int nt = 0; nt < 8; nt++)
            #pragma unroll
            for (int e = 0; e < 4; e++) sc[nt][e] = 0.f;
        #pragma unroll
        for (int nt2 = 0; nt2 < 4; nt2++) {
            #pragma unroll
            for (int kb = 0; kb < 4; kb++) {
                uint32_t bf[4];
                ldsm4(bf, uK[s] + (nt2*16 + lm) * 144 + kb*32 + lh16);
                mma16816(sc[2*nt2],     qf[kb], bf[0], bf[2]);
                mma16816(sc[2*nt2 + 1], qf[kb], bf[1], bf[3]);
            }
        }

        // online softmax (base-2), rows g / g+8, quad max reduce
        float tm0 = -1e30f, tm1 = -1e30f;
        #pragma unroll
        for (int nt = 0; nt < 8; nt++) {
            tm0 = fmaxf(tm0, fmaxf(sc[nt][0], sc[nt][1]));
            tm1 = fmaxf(tm1, fmaxf(sc[nt][2], sc[nt][3]));
        }
        tm0 = fmaxf(tm0, __shfl_xor_sync(0xffffffffu, tm0, 1));
        tm0 = fmaxf(tm0, __shfl_xor_sync(0xffffffffu, tm0, 2));
        tm1 = fmaxf(tm1, __shfl_xor_sync(0xffffffffu, tm1, 1));
        tm1 = fmaxf(tm1, __shfl_xor_sync(0xffffffffu, tm1, 2));

        const float nm0 = fmaxf(m0v, tm0), nm1 = fmaxf(m1v, tm1);
        const float es0 = ex2f(m0v - nm0), es1 = ex2f(m1v - nm1);
        m0v = nm0; m1v = nm1;

        // probabilities as packed fp16: exp via f16x2 MUFU (results ARE P frags)
        uint32_t pr0[8], pr1[8];
        #pragma unroll
        for (int nt = 0; nt < 8; nt++) {
            pr0[nt] = h2ex2(pkh2(sc[nt][0] - nm0, sc[nt][1] - nm0));
            pr1[nt] = h2ex2(pkh2(sc[nt][2] - nm1, sc[nt][3] - nm1));
        }

        // rescale accumulator
        #pragma unroll
        for (int d = 0; d < 8; d++) {
            ao[d][0] *= es0; ao[d][1] *= es0;
            ao[d][2] *= es1; ao[d][3] *= es1;
        }

        // O += P V ; row sums via ones-MMA (exact fp32 cross-quad sum)
        float su[4] = {0.f, 0.f, 0.f, 0.f};
        #pragma unroll
        for (int kb2 = 0; kb2 < 4; kb2++) {
            uint32_t pa[4];
            pa[0] = pr0[2*kb2];     pa[1] = pr1[2*kb2];
            pa[2] = pr0[2*kb2 + 1]; pa[3] = pr1[2*kb2 + 1];
            mma16816(su, pa, ONESH2, ONESH2);
            #pragma unroll
            for (int dp = 0; dp < 4; dp++) {
                uint32_t vf[4];
                ldsm4t(vf, uV[s] + (kb2*16 + lm) * 144 + dp*32 + lh16);
                mma16816(ao[2*dp],     pa, vf[0], vf[1]);
                mma16816(ao[2*dp + 1], pa, vf[2], vf[3]);
            }
        }
        l0 = l0 * es0 + su[0];
        l1 = l1 * es1 + su[2];
    }

    const float inv0 = 1.f / l0, inv1 = 1.f / l1;
    const int r0 = qt * 128 + wid * 16 + g;
    const size_t mrow0 = (size_t)(b * Tn + r0) * Dn;
    const size_t mrow1 = (size_t)(b * Tn + r0 + 8) * Dn;
    #pragma unroll
    for (int dt = 0; dt < 8; dt++) {
        const int c = h * 64 + dt * 8 + 2 * t;
        *(uint32_t*)(O + mrow0 + c) = pkh2(ao[dt][0] * inv0, ao[dt][1] * inv0);
        *(uint32_t*)(O + mrow1 + c) = pkh2(ao[dt][2] * inv1, ao[dt][3] * inv1);
    }
}

// ---------------------------------------------------------------------------
extern "C" void kernel_launch(void* const* d_in, const int* in_sizes, int n_in,
                              void* d_out, int out_size)
{
    (void)in_sizes; (void)n_in; (void)out_size;
    const float* x  = (const float*)d_in[0];
    const float* Wq = (const float*)d_in[1];
    const float* bq = (const float*)d_in[2];
    const float* Wk = (const float*)d_in[3];
    const float* bk = (const float*)d_in[4];
    const float* Wv = (const float*)d_in[5];
    const float* bv = (const float*)d_in[6];
    const float* Wo = (const float*)d_in[7];
    const float* bo = (const float*)d_in[8];
    float* out = (float*)d_out;

    __half *Qh, *Kh, *Vh, *attn;
    cudaGetSymbolAddress((void**)&Qh,   g_Qh);
    cudaGetSymbolAddress((void**)&Kh,   g_Kh);
    cudaGetSymbolAddress((void**)&Vh,   g_Vh);
    cudaGetSymbolAddress((void**)&attn, g_attn);

    cudaFuncSetAttribute(gemm_qkv_kernel, cudaFuncAttributeMaxDynamicSharedMemorySize, GSMEM);
    cudaFuncSetAttribute(gemm_o_kernel,   cudaFuncAttributeMaxDynamicSharedMemorySize, GSMEM);
    cudaFuncSetAttribute(attn_h_kernel,   cudaFuncAttributeMaxDynamicSharedMemorySize, ATTN_SMEM3);

    const int total = CVT_TOTAL + TBL_TOTAL;
    cvt_all_kernel<<<(total + 255) / 256, 256>>>(x, Wq, Wk, Wv, Wo);

    gemm_qkv_kernel<<<dim3(24, 32), 256, GSMEM>>>(bq, bk, bv);

    attn_h_kernel<<<dim3(Tn / 128, Bn * Hn), 256, ATTN_SMEM3>>>(Qh, Kh, Vh, attn);

    gemm_o_kernel<<<dim3(8, 32), 256, GSMEM>>>(bo, out);
}

// round 14
// speedup vs baseline: 1.5509x; 1.5509x over previous
#include <cuda_runtime.h>
#include <cuda_fp16.h>
#include <math.h>
#include <cstdint>

// ---------------------------------------------------------------------------
// RoPE MHA on GB300 (sm_103 family-generic target).
// R13: R11 structure + register-neutral f16x2-exp softmax (exp fused into the
//      PV loop, ones-MMA row sums, occupancy pinned via __launch_bounds__).
// ---------------------------------------------------------------------------

namespace {
constexpr int Bn=2, Tn=2048, Hn=16, Dhn=64, Dn=1024, Mn=4096;
constexpr float QSC = 0.125f * 1.44269504088896340736f;   // 1/sqrt(64) * log2(e)
}

__device__ __half g_xh[(size_t)Mn*Dn];
__device__ __half g_Wqh[(size_t)Dn*Dn];
__device__ __half g_Wkh[(size_t)Dn*Dn];
__device__ __half g_Wvh[(size_t)Dn*Dn];
__device__ __half g_Woh[(size_t)Dn*Dn];
__device__ __half g_Qh[(size_t)Mn*Dn];
__device__ __half g_Kh[(size_t)Mn*Dn];
__device__ __half g_Vh[(size_t)Mn*Dn];
__device__ __half g_attn[(size_t)Mn*Dn];
__device__ float2 g_tbl[(size_t)Tn*32];        // (cos, sin) per (t, i)

// ----------------------------- helpers ------------------------------------
__device__ __forceinline__ uint32_t smem_u32(const void* p) {
    uint32_t a;
    asm("{ .reg .u64 t; cvta.to.shared.u64 t, %1; cvt.u32.u64 %0, t; }"
        : "=r"(a) : "l"(p));
    return a;
}
__device__ __forceinline__ uint32_t pkh2(float lo, float hi) {
    __half2 h = __floats2half2_rn(lo, hi);
    return *reinterpret_cast<uint32_t*>(&h);
}
__device__ __forceinline__ float ex2f(float x) {
    float r;
    asm("ex2.approx.f32 %0, %1;" : "=f"(r) : "f"(x));
    return r;
}
__device__ __forceinline__ uint32_t h2ex2(uint32_t x) {   // packed 2^h for half2
    uint32_t r;
    asm("ex2.approx.f16x2 %0, %1;" : "=r"(r) : "r"(x));
    return r;
}
__device__ __forceinline__ void mma16816(float* c, const uint32_t* a,
                                         uint32_t b0, uint32_t b1) {
    asm volatile(
        "mma.sync.aligned.m16n8k16.row.col.f32.f16.f16.f32 "
        "{%0,%1,%2,%3},{%4,%5,%6,%7},{%8,%9},{%0,%1,%2,%3};"
        : "+f"(c[0]), "+f"(c[1]), "+f"(c[2]), "+f"(c[3])
        : "r"(a[0]), "r"(a[1]), "r"(a[2]), "r"(a[3]), "r"(b0), "r"(b1));
}
__device__ __forceinline__ void ldsm4(uint32_t* r, uint32_t addr) {
    asm volatile("ldmatrix.sync.aligned.m8n8.x4.shared.b16 {%0,%1,%2,%3}, [%4];"
        : "=r"(r[0]), "=r"(r[1]), "=r"(r[2]), "=r"(r[3]) : "r"(addr));
}
__device__ __forceinline__ void ldsm4t(uint32_t* r, uint32_t addr) {
    asm volatile("ldmatrix.sync.aligned.m8n8.x4.trans.shared.b16 {%0,%1,%2,%3}, [%4];"
        : "=r"(r[0]), "=r"(r[1]), "=r"(r[2]), "=r"(r[3]) : "r"(addr));
}
#define CP_ASYNC16(dst, src) \
    asm volatile("cp.async.cg.shared.global [%0], [%1], 16;" :: "r"(dst), "l"(src))
#define CP_COMMIT() asm volatile("cp.async.commit_group;" ::: "memory")
#define CP_WAIT(n)  asm volatile("cp.async.wait_group %0;" :: "n"(n) : "memory")

// ---------------------------------------------------------------------------
// Fused fp32->fp16 conversion of x + 4 weights, AND RoPE table (one launch).
// ---------------------------------------------------------------------------
namespace {
constexpr int XN4 = Mn*Dn/4, WN4 = Dn*Dn/4;
constexpr int CVT_TOTAL = XN4 + 4 * WN4;       // 2,097,152
constexpr int TBL_TOTAL = Tn * 32;             // 65,536
}

__global__ void cvt_all_kernel(const float* __restrict__ x,
                               const float* __restrict__ Wq, const float* __restrict__ Wk,
                               const float* __restrict__ Wv, const float* __restrict__ Wo)
{
    const int i = blockIdx.x * blockDim.x + threadIdx.x;
    if (i >= CVT_TOTAL) {
        const int idx = i - CVT_TOTAL;
        if (idx < TBL_TOTAL) {
            const int fi = idx & 31, t = idx >> 5;
            const float invf = 1.0f / powf(10000.0f, (float)fi * (1.0f / 32.0f));
            float sn, cs;
            sincosf((float)t * invf, &sn, &cs);
            g_tbl[idx] = make_float2(cs, sn);
        }
        return;
    }
    const float* src; __half* dst; int off;
    if (i < XN4)            { src = x;  dst = g_xh;  off = i; }
    else {
        const int j = i - XN4, sel = j / WN4; off = j % WN4;
        src = (sel == 0) ? Wq : (sel == 1) ? Wk : (sel == 2) ? Wv : Wo;
        dst = (sel == 0) ? g_Wqh : (sel == 1) ? g_Wkh : (sel == 2) ? g_Wvh : g_Woh;
    }
    const float4 v = ((const float4*)src)[off];
    uint2 o;
    o.x = pkh2(v.x, v.y);
    o.y = pkh2(v.z, v.w);
    ((uint2*)dst)[off] = o;
}

// ===========================================================================
// GEMM mainloop: 128x128 tile, 8 warps as 4m x 2n (32 rows x 64 cols each),
//   3-stage cp.async, K-chunk 64, 144B smem row stride.
// ===========================================================================
namespace {
constexpr int STGB  = 18432;
constexpr int GSMEM = 6 * STGB;
constexpr int NIT   = 16;
}

__device__ __forceinline__ void gload64(uint32_t dst, const __half* src,
                                        int row, int hf, int k0)
{
    const char* s = (const char*)(src + (size_t)row * 1024 + k0 + hf * 32);
    const uint32_t d = dst + row * 144 + hf * 64;
    CP_ASYNC16(d,      s);
    CP_ASYNC16(d + 16, s + 16);
    CP_ASYNC16(d + 32, s + 32);
    CP_ASYNC16(d + 48, s + 48);
}

__device__ __forceinline__ void gemm_mainloop(const __half* Ag, const __half* Wg,
                                              uint32_t ub, float (&acc)[2][8][4])
{
    const int tid  = threadIdx.x;
    const int lane = tid & 31;
    const int wid  = tid >> 5;
    const int lm   = lane & 15;
    const int lh16 = (lane >> 4) << 4;
    const int wm = wid & 3, wn = wid >> 2;
    const int row = tid >> 1, hf = tid & 1;

    #pragma unroll
    for (int i = 0; i < 2; i++)
        #pragma unroll
        for (int j = 0; j < 8; j++)
            #pragma unroll
            for (int e = 0; e < 4; e++) acc[i][j][e] = 0.f;

    gload64(ub,            Ag, row, hf, 0);
    gload64(ub + 3 * STGB, Wg, row, hf, 0);
    CP_COMMIT();
    gload64(ub + STGB,            Ag, row, hf, 64);
    gload64(ub + 3 * STGB + STGB, Wg, row, hf, 64);
    CP_COMMIT();

    for (int i = 0; i < NIT; i++) {
        CP_WAIT(1);
        __syncthreads();
        if (i + 2 < NIT) {
            const int s = (i + 2) % 3;
            gload64(ub + s * STGB,       Ag, row, hf, (i + 2) * 64);
            gload64(ub + (3 + s) * STGB, Wg, row, hf, (i + 2) * 64);
        }
        CP_COMMIT();

        const uint32_t uA = ub + (i % 3) * STGB;
        const uint32_t uW = ub + (3 + i % 3) * STGB;
        #pragma unroll
        for (int kb = 0; kb < 4; kb++) {
            uint32_t af[2][4];
            #pragma unroll
            for (int mt = 0; mt < 2; mt++)
                ldsm4(af[mt], uA + (wm*32 + mt*16 + lm) * 144 + kb*32 + lh16);
            uint32_t bf[4][4];
            #pragma unroll
            for (int p = 0; p < 4; p++)
                ldsm4(bf[p], uW + (wn*64 + p*16 + lm) * 144 + kb*32 + lh16);
            #pragma unroll
            for (int mt = 0; mt < 2; mt++)
                #pragma unroll
                for (int nt = 0; nt < 8; nt++) {
                    const int p = nt >> 1, q = nt & 1;
                    mma16816(acc[mt][nt], af[mt], bf[p][q], bf[p][2 + q]);
                }
        }
    }
}

// ===========================================================================
// Fused QKV projection + RoPE epilogue. grid (24, 32): which = bx/8.
// ===========================================================================
__global__ __launch_bounds__(256)
void gemm_qkv_kernel(const float* __restrict__ bq, const float* __restrict__ bk,
                     const float* __restrict__ bv)
{
    extern __shared__ char smc[];
    const uint32_t ub = smem_u32(smc);

    const int which = blockIdx.x >> 3;
    const int n0 = (blockIdx.x & 7) * 128;
    const int m0 = blockIdx.y * 128;

    const __half* Wh = (which == 0) ? g_Wqh : (which == 1) ? g_Wkh : g_Wvh;
    const float* bias = (which == 0) ? bq : (which == 1) ? bk : bv;

    float acc[2][8][4];
    gemm_mainloop(g_xh + (size_t)m0 * 1024, Wh + (size_t)n0 * 1024, ub, acc);

    const int tid = threadIdx.x, lane = tid & 31, wid = tid >> 5;
    const int g = lane >> 2, t = lane & 3;
    const int wm = wid & 3, wn = wid >> 2;

    const int hcol = n0 + wn * 64;       // head-aligned column base
    const int h    = hcol >> 6;

    if (which == 2) {
        #pragma unroll
        for (int mt = 0; mt < 2; mt++) {
            const int r0 = m0 + wm * 32 + mt * 16 + g;
            const int bb = r0 >> 11, tt0 = r0 & (Tn - 1);
            const size_t b0 = ((size_t)(bb * Hn + h) * Tn + tt0) * Dhn;
            const size_t b1 = b0 + 8 * Dhn;
            #pragma unroll
            for (int nt = 0; nt < 8; nt++) {
                const int d = nt * 8 + 2 * t;
                const float2 bv2 = *(const float2*)(bias + hcol + d);
                *(uint32_t*)(g_Vh + b0 + d) = pkh2(acc[mt][nt][0] + bv2.x, acc[mt][nt][1] + bv2.y);
                *(uint32_t*)(g_Vh + b1 + d) = pkh2(acc[mt][nt][2] + bv2.x, acc[mt][nt][3] + bv2.y);
            }
        }
    } else {
        __half* C = (which == 0) ? g_Qh : g_Kh;
        const float sc = (which == 0) ? QSC : 1.0f;
        #pragma unroll
        for (int mt = 0; mt < 2; mt++) {
            const int r0 = m0 + wm * 32 + mt * 16 + g;
            const int bb = r0 >> 11, tt0 = r0 & (Tn - 1), tt1 = tt0 + 8;
            const size_t b0 = ((size_t)(bb * Hn + h) * Tn + tt0) * Dhn;
            const size_t b1 = b0 + 8 * Dhn;
            #pragma unroll
            for (int nt = 0; nt < 4; nt++) {
                const int i0 = nt * 8 + 2 * t;           // d in [0,32)
                const float2 bl = *(const float2*)(bias + hcol + i0);
                const float2 bh = *(const float2*)(bias + hcol + i0 + 32);
                const float4 ca = *(const float4*)(&g_tbl[(size_t)tt0 * 32 + i0]);
                const float4 cb = *(const float4*)(&g_tbl[(size_t)tt1 * 32 + i0]);
                {
                    const float xl0 = acc[mt][nt][0] + bl.x, xl1 = acc[mt][nt][1] + bl.y;
                    const float xh0 = acc[mt][nt+4][0] + bh.x, xh1 = acc[mt][nt+4][1] + bh.y;
                    *(uint32_t*)(C + b0 + i0)      = pkh2((xl0 * ca.x - xh0 * ca.y) * sc,
                                                          (xl1 * ca.z - xh1 * ca.w) * sc);
                    *(uint32_t*)(C + b0 + i0 + 32) = pkh2((xh0 * ca.x + xl0 * ca.y) * sc,
                                                          (xh1 * ca.z + xl1 * ca.w) * sc);
                }
                {
                    const float xl0 = acc[mt][nt][2] + bl.x, xl1 = acc[mt][nt][3] + bl.y;
                    const float xh0 = acc[mt][nt+4][2] + bh.x, xh1 = acc[mt][nt+4][3] + bh.y;
                    *(uint32_t*)(C + b1 + i0)      = pkh2((xl0 * cb.x - xh0 * cb.y) * sc,
                                                          (xl1 * cb.z - xh1 * cb.w) * sc);
                    *(uint32_t*)(C + b1 + i0 + 32) = pkh2((xh0 * cb.x + xl0 * cb.y) * sc,
                                                          (xh1 * cb.z + xl1 * cb.w) * sc);
                }
            }
        }
    }
}

// ===========================================================================
// O projection: out[m,n] = attn[m,:] x Wo[n,:] + bo, fp32 row-major.
// ===========================================================================
__global__ __launch_bounds__(256)
void gemm_o_kernel(const float* __restrict__ bias, float* __restrict__ out)
{
    extern __shared__ char smc[];
    const uint32_t ub = smem_u32(smc);

    const int n0 = blockIdx.x * 128;
    const int m0 = blockIdx.y * 128;

    float acc[2][8][4];
    gemm_mainloop(g_attn + (size_t)m0 * 1024, g_Woh + (size_t)n0 * 1024, ub, acc);

    const int tid = threadIdx.x, lane = tid & 31, wid = tid >> 5;
    const int g = lane >> 2, t = lane & 3;
    const int wm = wid & 3, wn = wid >> 2;

    #pragma unroll
    for (int mt = 0; mt < 2; mt++) {
        const int r0 = m0 + wm * 32 + mt * 16 + g;
        #pragma unroll
        for (int nt = 0; nt < 8; nt++) {
            const int c = n0 + wn * 64 + nt * 8 + 2 * t;
            const float2 bv2 = *(const float2*)(bias + c);
            *(float2*)(out + (size_t)r0 * Dn + c) =
                make_float2(acc[mt][nt][0] + bv2.x, acc[mt][nt][1] + bv2.y);
            *(float2*)(out + (size_t)(r0 + 8) * Dn + c) =
                make_float2(acc[mt][nt][2] + bv2.x, acc[mt][nt][3] + bv2.y);
        }
    }
}

// ===========================================================================
// Flash attention: 128q/CTA, 256 thr, 3-stage cp.async K/V ring,
// exp2-domain softmax. f16x2 exp fused into PV loop (register-neutral),
// row sums via ones-MMA. Occupancy pinned at 2 CTAs/SM.
// ===========================================================================
namespace {
constexpr int ATTN_SMEM3 = 18432 + 6 * 9216;
constexpr uint32_t ONESH2 = 0x3C003C00u;       // half2(1.0, 1.0)
}

__global__ __launch_bounds__(256, 2)
void attn_h_kernel(const __half* __restrict__ Q, const __half* __restrict__ K,
                   const __half* __restrict__ V, __half* __restrict__ O)
{
    extern __shared__ char asmc[];
    const uint32_t ub = smem_u32(asmc);

    const int tid  = threadIdx.x;
    const int lane = tid & 31;
    const int wid  = tid >> 5;
    const int g = lane >> 2, t = lane & 3;
    const int lm   = lane & 15;
    const int lh16 = (lane >> 4) << 4;

    const int qt = blockIdx.x, bh = blockIdx.y;
    const int b = bh >> 4, h = bh & 15;

    const char* Qg = (const char*)(Q + (size_t)bh * Tn * 64 + (size_t)qt * 128 * 64);
    const char* Kg = (const char*)(K + (size_t)bh * Tn * 64);
    const char* Vg = (const char*)(V + (size_t)bh * Tn * 64);

    const uint32_t uQ = ub;
    uint32_t uK[3], uV[3];
    #pragma unroll
    for (int s = 0; s < 3; s++) {
        uK[s] = ub + 18432 + s * 9216;
        uV[s] = ub + 18432 + (3 + s) * 9216;
    }

    const int kr = tid >> 2, ko = (tid & 3) * 32;

    // prologue: Q + K/V tiles 0 and 1
    {
        const int qrow = tid >> 1, qhf = tid & 1;
        const uint32_t qd = uQ + qrow * 144 + qhf * 64;
        const char* qs = Qg + qrow * 128 + qhf * 64;
        CP_ASYNC16(qd,      qs);
        CP_ASYNC16(qd + 16, qs + 16);
        CP_ASYNC16(qd + 32, qs + 32);
        CP_ASYNC16(qd + 48, qs + 48);
        CP_ASYNC16(uK[0] + kr * 144 + ko,      Kg + kr * 128 + ko);
        CP_ASYNC16(uK[0] + kr * 144 + ko + 16, Kg + kr * 128 + ko + 16);
        CP_ASYNC16(uV[0] + kr * 144 + ko,      Vg + kr * 128 + ko);
        CP_ASYNC16(uV[0] + kr * 144 + ko + 16, Vg + kr * 128 + ko + 16);
        CP_COMMIT();
        CP_ASYNC16(uK[1] + kr * 144 + ko,      Kg + 8192 + kr * 128 + ko);
        CP_ASYNC16(uK[1] + kr * 144 + ko + 16, Kg + 8192 + kr * 128 + ko + 16);
        CP_ASYNC16(uV[1] + kr * 144 + ko,      Vg + 8192 + kr * 128 + ko);
        CP_ASYNC16(uV[1] + kr * 144 + ko + 16, Vg + 8192 + kr * 128 + ko + 16);
        CP_COMMIT();
    }

    CP_WAIT(1);
    __syncthreads();

    // Q fragments (pre-scaled by 0.125*log2e in the QKV epilogue)
    uint32_t qf[4][4];
    #pragma unroll
    for (int kb = 0; kb < 4; kb++)
        ldsm4(qf[kb], uQ + (wid*16 + lm) * 144 + kb*32 + lh16);

    float ao[8][4];
    #pragma unroll
    for (int d = 0; d < 8; d++)
        #pragma unroll
        for (int e = 0; e < 4; e++) ao[d][e] = 0.f;
    float m0v = -1e30f, m1v = -1e30f, l0 = 0.f, l1 = 0.f;

    for (int i = 0; i < 32; i++) {
        if (i > 0) {
            CP_WAIT(1);
            __syncthreads();
        }
        if (i + 2 < 32) {
            const int s = (i + 2) % 3;
            const char* Kn = Kg + (size_t)(i + 2) * 8192;
            const char* Vn = Vg + (size_t)(i + 2) * 8192;
            CP_ASYNC16(uK[s] + kr * 144 + ko,      Kn + kr * 128 + ko);
            CP_ASYNC16(uK[s] + kr * 144 + ko + 16, Kn + kr * 128 + ko + 16);
            CP_ASYNC16(uV[s] + kr * 144 + ko,      Vn + kr * 128 + ko);
            CP_ASYNC16(uV[s] + kr * 144 + ko + 16, Vn + kr * 128 + ko + 16);
        }
        CP_COMMIT();

        const int s = i % 3;

        // S = Q K^T  (16q x 64k per warp), log2 domain
        float sc[8][4];
        #pragma unroll
        for (int nt = 0; nt < 8; nt++)
            #pragma unroll
            for (int e = 0; e < 4; e++) sc[nt][e] = 0.f;
        #pragma unroll
        for (int nt2 = 0; nt2 < 4; nt2++) {
            #pragma unroll
            for (int kb = 0; kb < 4; kb++) {
                uint32_t bf[4];
                ldsm4(bf, uK[s] + (nt2*16 + lm) * 144 + kb*32 + lh16);
                mma16816(sc[2*nt2],     qf[kb], bf[0], bf[2]);
                mma16816(sc[2*nt2 + 1], qf[kb], bf[1], bf[3]);
            }
        }

        // online softmax (base-2), rows g / g+8, quad max reduce
        float tm0 = -1e30f, tm1 = -1e30f;
        #pragma unroll
        for (int nt = 0; nt < 8; nt++) {
            tm0 = fmaxf(tm0, fmaxf(sc[nt][0], sc[nt][1]));
            tm1 = fmaxf(tm1, fmaxf(sc[nt][2], sc[nt][3]));
        }
        tm0 = fmaxf(tm0, __shfl_xor_sync(0xffffffffu, tm0, 1));
        tm0 = fmaxf(tm0, __shfl_xor_sync(0xffffffffu, tm0, 2));
        tm1 = fmaxf(tm1, __shfl_xor_sync(0xffffffffu, tm1, 1));
        tm1 = fmaxf(tm1, __shfl_xor_sync(0xffffffffu, tm1, 2));

        const float nm0 = fmaxf(m0v, tm0), nm1 = fmaxf(m1v, tm1);
        const float es0 = ex2f(m0v - nm0), es1 = ex2f(m1v - nm1);
        m0v = nm0; m1v = nm1;

        // rescale accumulator
        #pragma unroll
        for (int d = 0; d < 8; d++) {
            ao[d][0] *= es0; ao[d][1] *= es0;
            ao[d][2] *= es1; ao[d][3] *= es1;
        }

        // O += P V with exp fused per-kb2 (only 4 packed P regs live at once);
        // row sums via ones-MMA (exact fp32 cross-quad sum of the fp16 P used).
        float su[4] = {0.f, 0.f, 0.f, 0.f};
        #pragma unroll
        for (int kb2 = 0; kb2 < 4; kb2++) {
            uint32_t pa[4];
            pa[0] = h2ex2(pkh2(sc[2*kb2][0]     - nm0, sc[2*kb2][1]     - nm0));
            pa[1] = h2ex2(pkh2(sc[2*kb2][2]     - nm1, sc[2*kb2][3]     - nm1));
            pa[2] = h2ex2(pkh2(sc[2*kb2 + 1][0] - nm0, sc[2*kb2 + 1][1] - nm0));
            pa[3] = h2ex2(pkh2(sc[2*kb2 + 1][2] - nm1, sc[2*kb2 + 1][3] - nm1));
            mma16816(su, pa, ONESH2, ONESH2);
            #pragma unroll
            for (int dp = 0; dp < 4; dp++) {
                uint32_t vf[4];
                ldsm4t(vf, uV[s] + (kb2*16 + lm) * 144 + dp*32 + lh16);
                mma16816(ao[2*dp],     pa, vf[0], vf[1]);
                mma16816(ao[2*dp + 1], pa, vf[2], vf[3]);
            }
        }
        l0 = l0 * es0 + su[0];
        l1 = l1 * es1 + su[2];
    }

    const float inv0 = 1.f / l0, inv1 = 1.f / l1;
    const int r0 = qt * 128 + wid * 16 + g;
    const size_t mrow0 = (size_t)(b * Tn + r0) * Dn;
    const size_t mrow1 = (size_t)(b * Tn + r0 + 8) * Dn;
    #pragma unroll
    for (int dt = 0; dt < 8; dt++) {
        const int c = h * 64 + dt * 8 + 2 * t;
        *(uint32_t*)(O + mrow0 + c) = pkh2(ao[dt][0] * inv0, ao[dt][1] * inv0);
        *(uint32_t*)(O + mrow1 + c) = pkh2(ao[dt][2] * inv1, ao[dt][3] * inv1);
    }
}

// ---------------------------------------------------------------------------
extern "C" void kernel_launch(void* const* d_in, const int* in_sizes, int n_in,
                              void* d_out, int out_size)
{
    (void)in_sizes; (void)n_in; (void)out_size;
    const float* x  = (const float*)d_in[0];
    const float* Wq = (const float*)d_in[1];
    const float* bq = (const float*)d_in[2];
    const float* Wk = (const float*)d_in[3];
    const float* bk = (const float*)d_in[4];
    const float* Wv = (const float*)d_in[5];
    const float* bv = (const float*)d_in[6];
    const float* Wo = (const float*)d_in[7];
    const float* bo = (const float*)d_in[8];
    float* out = (float*)d_out;

    __half *Qh, *Kh, *Vh, *attn;
    cudaGetSymbolAddress((void**)&Qh,   g_Qh);
    cudaGetSymbolAddress((void**)&Kh,   g_Kh);
    cudaGetSymbolAddress((void**)&Vh,   g_Vh);
    cudaGetSymbolAddress((void**)&attn, g_attn);

    cudaFuncSetAttribute(gemm_qkv_kernel, cudaFuncAttributeMaxDynamicSharedMemorySize, GSMEM);
    cudaFuncSetAttribute(gemm_o_kernel,   cudaFuncAttributeMaxDynamicSharedMemorySize, GSMEM);
    cudaFuncSetAttribute(attn_h_kernel,   cudaFuncAttributeMaxDynamicSharedMemorySize, ATTN_SMEM3);

    const int total = CVT_TOTAL + TBL_TOTAL;
    cvt_all_kernel<<<(total + 255) / 256, 256>>>(x, Wq, Wk, Wv, Wo);

    gemm_qkv_kernel<<<dim3(24, 32), 256, GSMEM>>>(bq, bk, bv);

    attn_h_kernel<<<dim3(Tn / 128, Bn * Hn), 256, ATTN_SMEM3>>>(Qh, Kh, Vh, attn);

    gemm_o_kernel<<<dim3(8, 32), 256, GSMEM>>>(bo, out);
}

// round 15
// speedup vs baseline: 1.7325x; 1.1171x over previous
#include <cuda_runtime.h>
#include <cuda_fp16.h>
#include <math.h>
#include <cstdint>

// ---------------------------------------------------------------------------
// RoPE MHA on GB300 (sm_103 family-generic target).
// R15: GEMM mainloop reshaped for occupancy: K-chunk 32, 3-stage ring,
//      80B row stride -> 61440B smem -> 2 CTAs/SM (was 1). Attention as R13.
// ---------------------------------------------------------------------------

namespace {
constexpr int Bn=2, Tn=2048, Hn=16, Dhn=64, Dn=1024, Mn=4096;
constexpr float QSC = 0.125f * 1.44269504088896340736f;   // 1/sqrt(64) * log2(e)
}

__device__ __half g_xh[(size_t)Mn*Dn];
__device__ __half g_Wqh[(size_t)Dn*Dn];
__device__ __half g_Wkh[(size_t)Dn*Dn];
__device__ __half g_Wvh[(size_t)Dn*Dn];
__device__ __half g_Woh[(size_t)Dn*Dn];
__device__ __half g_Qh[(size_t)Mn*Dn];
__device__ __half g_Kh[(size_t)Mn*Dn];
__device__ __half g_Vh[(size_t)Mn*Dn];
__device__ __half g_attn[(size_t)Mn*Dn];
__device__ float2 g_tbl[(size_t)Tn*32];        // (cos, sin) per (t, i)

// ----------------------------- helpers ------------------------------------
__device__ __forceinline__ uint32_t smem_u32(const void* p) {
    uint32_t a;
    asm("{ .reg .u64 t; cvta.to.shared.u64 t, %1; cvt.u32.u64 %0, t; }"
        : "=r"(a) : "l"(p));
    return a;
}
__device__ __forceinline__ uint32_t pkh2(float lo, float hi) {
    __half2 h = __floats2half2_rn(lo, hi);
    return *reinterpret_cast<uint32_t*>(&h);
}
__device__ __forceinline__ float ex2f(float x) {
    float r;
    asm("ex2.approx.f32 %0, %1;" : "=f"(r) : "f"(x));
    return r;
}
__device__ __forceinline__ uint32_t h2ex2(uint32_t x) {   // packed 2^h for half2
    uint32_t r;
    asm("ex2.approx.f16x2 %0, %1;" : "=r"(r) : "r"(x));
    return r;
}
__device__ __forceinline__ void mma16816(float* c, const uint32_t* a,
                                         uint32_t b0, uint32_t b1) {
    asm volatile(
        "mma.sync.aligned.m16n8k16.row.col.f32.f16.f16.f32 "
        "{%0,%1,%2,%3},{%4,%5,%6,%7},{%8,%9},{%0,%1,%2,%3};"
        : "+f"(c[0]), "+f"(c[1]), "+f"(c[2]), "+f"(c[3])
        : "r"(a[0]), "r"(a[1]), "r"(a[2]), "r"(a[3]), "r"(b0), "r"(b1));
}
__device__ __forceinline__ void ldsm4(uint32_t* r, uint32_t addr) {
    asm volatile("ldmatrix.sync.aligned.m8n8.x4.shared.b16 {%0,%1,%2,%3}, [%4];"
        : "=r"(r[0]), "=r"(r[1]), "=r"(r[2]), "=r"(r[3]) : "r"(addr));
}
__device__ __forceinline__ void ldsm4t(uint32_t* r, uint32_t addr) {
    asm volatile("ldmatrix.sync.aligned.m8n8.x4.trans.shared.b16 {%0,%1,%2,%3}, [%4];"
        : "=r"(r[0]), "=r"(r[1]), "=r"(r[2]), "=r"(r[3]) : "r"(addr));
}
#define CP_ASYNC16(dst, src) \
    asm volatile("cp.async.cg.shared.global [%0], [%1], 16;" :: "r"(dst), "l"(src))
#define CP_COMMIT() asm volatile("cp.async.commit_group;" ::: "memory")
#define CP_WAIT(n)  asm volatile("cp.async.wait_group %0;" :: "n"(n) : "memory")

// ---------------------------------------------------------------------------
// Fused fp32->fp16 conversion of x + 4 weights, AND RoPE table (one launch).
// ---------------------------------------------------------------------------
namespace {
constexpr int XN4 = Mn*Dn/4, WN4 = Dn*Dn/4;
constexpr int CVT_TOTAL = XN4 + 4 * WN4;       // 2,097,152
constexpr int TBL_TOTAL = Tn * 32;             // 65,536
}

__global__ void cvt_all_kernel(const float* __restrict__ x,
                               const float* __restrict__ Wq, const float* __restrict__ Wk,
                               const float* __restrict__ Wv, const float* __restrict__ Wo)
{
    const int i = blockIdx.x * blockDim.x + threadIdx.x;
    if (i >= CVT_TOTAL) {
        const int idx = i - CVT_TOTAL;
        if (idx < TBL_TOTAL) {
            const int fi = idx & 31, t = idx >> 5;
            const float invf = 1.0f / powf(10000.0f, (float)fi * (1.0f / 32.0f));
            float sn, cs;
            sincosf((float)t * invf, &sn, &cs);
            g_tbl[idx] = make_float2(cs, sn);
        }
        return;
    }
    const float* src; __half* dst; int off;
    if (i < XN4)            { src = x;  dst = g_xh;  off = i; }
    else {
        const int j = i - XN4, sel = j / WN4; off = j % WN4;
        src = (sel == 0) ? Wq : (sel == 1) ? Wk : (sel == 2) ? Wv : Wo;
        dst = (sel == 0) ? g_Wqh : (sel == 1) ? g_Wkh : (sel == 2) ? g_Wvh : g_Woh;
    }
    const float4 v = ((const float4*)src)[off];
    uint2 o;
    o.x = pkh2(v.x, v.y);
    o.y = pkh2(v.z, v.w);
    ((uint2*)dst)[off] = o;
}

// ===========================================================================
// GEMM mainloop: 128x128 tile, 8 warps as 4m x 2n (32 rows x 64 cols each).
//   K-chunk 32, 3-stage cp.async ring, 80B smem row stride (16B-aligned,
//   ldsm start banks 4*{0,5,2,7,4,1,6,3} -> conflict-free).
//   smem: A stages 0..2, W stages 3..5, each 10240B -> 61440B total
//   -> 2 CTAs/SM.
// ===========================================================================
namespace {
constexpr int STGB  = 10240;           // 128 rows * 80B
constexpr int GSMEM = 6 * STGB;        // 61440 bytes
constexpr int NIT   = 32;              // 1024 / 32
}

__device__ __forceinline__ void gload32(uint32_t dst, const __half* src,
                                        int row, int hf, int k0)
{
    const char* s = (const char*)(src + (size_t)row * 1024 + k0 + hf * 16);
    const uint32_t d = dst + row * 80 + hf * 32;
    CP_ASYNC16(d,      s);
    CP_ASYNC16(d + 16, s + 16);
}

__device__ __forceinline__ void gemm_mainloop(const __half* Ag, const __half* Wg,
                                              uint32_t ub, float (&acc)[2][8][4])
{
    const int tid  = threadIdx.x;
    const int lane = tid & 31;
    const int wid  = tid >> 5;
    const int lm   = lane & 15;
    const int lh16 = (lane >> 4) << 4;
    const int wm = wid & 3, wn = wid >> 2;
    const int row = tid >> 1, hf = tid & 1;

    #pragma unroll
    for (int i = 0; i < 2; i++)
        #pragma unroll
        for (int j = 0; j < 8; j++)
            #pragma unroll
            for (int e = 0; e < 4; e++) acc[i][j][e] = 0.f;

    gload32(ub,            Ag, row, hf, 0);
    gload32(ub + 3 * STGB, Wg, row, hf, 0);
    CP_COMMIT();
    gload32(ub + STGB,            Ag, row, hf, 32);
    gload32(ub + 3 * STGB + STGB, Wg, row, hf, 32);
    CP_COMMIT();

    for (int i = 0; i < NIT; i++) {
        CP_WAIT(1);
        __syncthreads();
        if (i + 2 < NIT) {
            const int s = (i + 2) % 3;
            gload32(ub + s * STGB,       Ag, row, hf, (i + 2) * 32);
            gload32(ub + (3 + s) * STGB, Wg, row, hf, (i + 2) * 32);
        }
        CP_COMMIT();

        const uint32_t uA = ub + (i % 3) * STGB;
        const uint32_t uW = ub + (3 + i % 3) * STGB;
        #pragma unroll
        for (int kb = 0; kb < 2; kb++) {
            uint32_t af[2][4];
            #pragma unroll
            for (int mt = 0; mt < 2; mt++)
                ldsm4(af[mt], uA + (wm*32 + mt*16 + lm) * 80 + kb*32 + lh16);
            uint32_t bf[4][4];
            #pragma unroll
            for (int p = 0; p < 4; p++)
                ldsm4(bf[p], uW + (wn*64 + p*16 + lm) * 80 + kb*32 + lh16);
            #pragma unroll
            for (int mt = 0; mt < 2; mt++)
                #pragma unroll
                for (int nt = 0; nt < 8; nt++) {
                    const int p = nt >> 1, q = nt & 1;
                    mma16816(acc[mt][nt], af[mt], bf[p][q], bf[p][2 + q]);
                }
        }
    }
}

// ===========================================================================
// Fused QKV projection + RoPE epilogue. grid (24, 32): which = bx/8.
// ===========================================================================
__global__ __launch_bounds__(256, 2)
void gemm_qkv_kernel(const float* __restrict__ bq, const float* __restrict__ bk,
                     const float* __restrict__ bv)
{
    extern __shared__ char smc[];
    const uint32_t ub = smem_u32(smc);

    const int which = blockIdx.x >> 3;
    const int n0 = (blockIdx.x & 7) * 128;
    const int m0 = blockIdx.y * 128;

    const __half* Wh = (which == 0) ? g_Wqh : (which == 1) ? g_Wkh : g_Wvh;
    const float* bias = (which == 0) ? bq : (which == 1) ? bk : bv;

    float acc[2][8][4];
    gemm_mainloop(g_xh + (size_t)m0 * 1024, Wh + (size_t)n0 * 1024, ub, acc);

    const int tid = threadIdx.x, lane = tid & 31, wid = tid >> 5;
    const int g = lane >> 2, t = lane & 3;
    const int wm = wid & 3, wn = wid >> 2;

    const int hcol = n0 + wn * 64;       // head-aligned column base
    const int h    = hcol >> 6;

    if (which == 2) {
        #pragma unroll
        for (int mt = 0; mt < 2; mt++) {
            const int r0 = m0 + wm * 32 + mt * 16 + g;
            const int bb = r0 >> 11, tt0 = r0 & (Tn - 1);
            const size_t b0 = ((size_t)(bb * Hn + h) * Tn + tt0) * Dhn;
            const size_t b1 = b0 + 8 * Dhn;
            #pragma unroll
            for (int nt = 0; nt < 8; nt++) {
                const int d = nt * 8 + 2 * t;
                const float2 bv2 = *(const float2*)(bias + hcol + d);
                *(uint32_t*)(g_Vh + b0 + d) = pkh2(acc[mt][nt][0] + bv2.x, acc[mt][nt][1] + bv2.y);
                *(uint32_t*)(g_Vh + b1 + d) = pkh2(acc[mt][nt][2] + bv2.x, acc[mt][nt][3] + bv2.y);
            }
        }
    } else {
        __half* C = (which == 0) ? g_Qh : g_Kh;
        const float sc = (which == 0) ? QSC : 1.0f;
        #pragma unroll
        for (int mt = 0; mt < 2; mt++) {
            const int r0 = m0 + wm * 32 + mt * 16 + g;
            const int bb = r0 >> 11, tt0 = r0 & (Tn - 1), tt1 = tt0 + 8;
            const size_t b0 = ((size_t)(bb * Hn + h) * Tn + tt0) * Dhn;
            const size_t b1 = b0 + 8 * Dhn;
            #pragma unroll
            for (int nt = 0; nt < 4; nt++) {
                const int i0 = nt * 8 + 2 * t;           // d in [0,32)
                const float2 bl = *(const float2*)(bias + hcol + i0);
                const float2 bh = *(const float2*)(bias + hcol + i0 + 32);
                const float4 ca = *(const float4*)(&g_tbl[(size_t)tt0 * 32 + i0]);
                const float4 cb = *(const float4*)(&g_tbl[(size_t)tt1 * 32 + i0]);
                {
                    const float xl0 = acc[mt][nt][0] + bl.x, xl1 = acc[mt][nt][1] + bl.y;
                    const float xh0 = acc[mt][nt+4][0] + bh.x, xh1 = acc[mt][nt+4][1] + bh.y;
                    *(uint32_t*)(C + b0 + i0)      = pkh2((xl0 * ca.x - xh0 * ca.y) * sc,
                                                          (xl1 * ca.z - xh1 * ca.w) * sc);
                    *(uint32_t*)(C + b0 + i0 + 32) = pkh2((xh0 * ca.x + xl0 * ca.y) * sc,
                                                          (xh1 * ca.z + xl1 * ca.w) * sc);
                }
                {
                    const float xl0 = acc[mt][nt][2] + bl.x, xl1 = acc[mt][nt][3] + bl.y;
                    const float xh0 = acc[mt][nt+4][2] + bh.x, xh1 = acc[mt][nt+4][3] + bh.y;
                    *(uint32_t*)(C + b1 + i0)      = pkh2((xl0 * cb.x - xh0 * cb.y) * sc,
                                                          (xl1 * cb.z - xh1 * cb.w) * sc);
                    *(uint32_t*)(C + b1 + i0 + 32) = pkh2((xh0 * cb.x + xl0 * cb.y) * sc,
                                                          (xh1 * cb.z + xl1 * cb.w) * sc);
                }
            }
        }
    }
}

// ===========================================================================
// O projection: out[m,n] = attn[m,:] x Wo[n,:] + bo, fp32 row-major.
// ===========================================================================
__global__ __launch_bounds__(256, 2)
void gemm_o_kernel(const float* __restrict__ bias, float* __restrict__ out)
{
    extern __shared__ char smc[];
    const uint32_t ub = smem_u32(smc);

    const int n0 = blockIdx.x * 128;
    const int m0 = blockIdx.y * 128;

    float acc[2][8][4];
    gemm_mainloop(g_attn + (size_t)m0 * 1024, g_Woh + (size_t)n0 * 1024, ub, acc);

    const int tid = threadIdx.x, lane = tid & 31, wid = tid >> 5;
    const int g = lane >> 2, t = lane & 3;
    const int wm = wid & 3, wn = wid >> 2;

    #pragma unroll
    for (int mt = 0; mt < 2; mt++) {
        const int r0 = m0 + wm * 32 + mt * 16 + g;
        #pragma unroll
        for (int nt = 0; nt < 8; nt++) {
            const int c = n0 + wn * 64 + nt * 8 + 2 * t;
            const float2 bv2 = *(const float2*)(bias + c);
            *(float2*)(out + (size_t)r0 * Dn + c) =
                make_float2(acc[mt][nt][0] + bv2.x, acc[mt][nt][1] + bv2.y);
            *(float2*)(out + (size_t)(r0 + 8) * Dn + c) =
                make_float2(acc[mt][nt][2] + bv2.x, acc[mt][nt][3] + bv2.y);
        }
    }
}

// ===========================================================================
// Flash attention: 128q/CTA, 256 thr, 3-stage cp.async K/V ring,
// exp2-domain softmax. f16x2 exp fused into PV loop (register-neutral),
// row sums via ones-MMA. Occupancy pinned at 2 CTAs/SM.
// ===========================================================================
namespace {
constexpr int ATTN_SMEM3 = 18432 + 6 * 9216;
constexpr uint32_t ONESH2 = 0x3C003C00u;       // half2(1.0, 1.0)
}

__global__ __launch_bounds__(256, 2)
void attn_h_kernel(const __half* __restrict__ Q, const __half* __restrict__ K,
                   const __half* __restrict__ V, __half* __restrict__ O)
{
    extern __shared__ char asmc[];
    const uint32_t ub = smem_u32(asmc);

    const int tid  = threadIdx.x;
    const int lane = tid & 31;
    const int wid  = tid >> 5;
    const int g = lane >> 2, t = lane & 3;
    const int lm   = lane & 15;
    const int lh16 = (lane >> 4) << 4;

    const int qt = blockIdx.x, bh = blockIdx.y;
    const int b = bh >> 4, h = bh & 15;

    const char* Qg = (const char*)(Q + (size_t)bh * Tn * 64 + (size_t)qt * 128 * 64);
    const char* Kg = (const char*)(K + (size_t)bh * Tn * 64);
    const char* Vg = (const char*)(V + (size_t)bh * Tn * 64);

    const uint32_t uQ = ub;
    uint32_t uK[3], uV[3];
    #pragma unroll
    for (int s = 0; s < 3; s++) {
        uK[s] = ub + 18432 + s * 9216;
        uV[s] = ub + 18432 + (3 + s) * 9216;
    }

    const int kr = tid >> 2, ko = (tid & 3) * 32;

    // prologue: Q + K/V tiles 0 and 1
    {
        const int qrow = tid >> 1, qhf = tid & 1;
        const uint32_t qd = uQ + qrow * 144 + qhf * 64;
        const char* qs = Qg + qrow * 128 + qhf * 64;
        CP_ASYNC16(qd,      qs);
        CP_ASYNC16(qd + 16, qs + 16);
        CP_ASYNC16(qd + 32, qs + 32);
        CP_ASYNC16(qd + 48, qs + 48);
        CP_ASYNC16(uK[0] + kr * 144 + ko,      Kg + kr * 128 + ko);
        CP_ASYNC16(uK[0] + kr * 144 + ko + 16, Kg + kr * 128 + ko + 16);
        CP_ASYNC16(uV[0] + kr * 144 + ko,      Vg + kr * 128 + ko);
        CP_ASYNC16(uV[0] + kr * 144 + ko + 16, Vg + kr * 128 + ko + 16);
        CP_COMMIT();
        CP_ASYNC16(uK[1] + kr * 144 + ko,      Kg + 8192 + kr * 128 + ko);
        CP_ASYNC16(uK[1] + kr * 144 + ko + 16, Kg + 8192 + kr * 128 + ko + 16);
        CP_ASYNC16(uV[1] + kr * 144 + ko,      Vg + 8192 + kr * 128 + ko);
        CP_ASYNC16(uV[1] + kr * 144 + ko + 16, Vg + 8192 + kr * 128 + ko + 16);
        CP_COMMIT();
    }

    CP_WAIT(1);
    __syncthreads();

    // Q fragments (pre-scaled by 0.125*log2e in the QKV epilogue)
    uint32_t qf[4][4];
    #pragma unroll
    for (int kb = 0; kb < 4; kb++)
        ldsm4(qf[kb], uQ + (wid*16 + lm) * 144 + kb*32 + lh16);

    float ao[8][4];
    #pragma unroll
    for (int d = 0; d < 8; d++)
        #pragma unroll
        for (int e = 0; e < 4; e++) ao[d][e] = 0.f;
    float m0v = -1e30f, m1v = -1e30f, l0 = 0.f, l1 = 0.f;

    for (int i = 0; i < 32; i++) {
        if (i > 0) {
            CP_WAIT(1);
            __syncthreads();
        }
        if (i + 2 < 32) {
            const int s = (i + 2) % 3;
            const char* Kn = Kg + (size_t)(i + 2) * 8192;
            const char* Vn = Vg + (size_t)(i + 2) * 8192;
            CP_ASYNC16(uK[s] + kr * 144 + ko,      Kn + kr * 128 + ko);
            CP_ASYNC16(uK[s] + kr * 144 + ko + 16, Kn + kr * 128 + ko + 16);
            CP_ASYNC16(uV[s] + kr * 144 + ko,      Vn + kr * 128 + ko);
            CP_ASYNC16(uV[s] + kr * 144 + ko + 16, Vn + kr * 128 + ko + 16);
        }
        CP_COMMIT();

        const int s = i % 3;

        // S = Q K^T  (16q x 64k per warp), log2 domain
        float sc[8][4];
        #pragma unroll
        for (int nt = 0; nt < 8; nt++)
            #pragma unroll
            for (int e = 0; e < 4; e++) sc[nt][e] = 0.f;
        #pragma unroll
        for (int nt2 = 0; nt2 < 4; nt2++) {
            #pragma unroll
            for (int kb = 0; kb < 4; kb++) {
                uint32_t bf[4];
                ldsm4(bf, uK[s] + (nt2*16 + lm) * 144 + kb*32 + lh16);
                mma16816(sc[2*nt2],     qf[kb], bf[0], bf[2]);
                mma16816(sc[2*nt2 + 1], qf[kb], bf[1], bf[3]);
            }
        }

        // online softmax (base-2), rows g / g+8, quad max reduce
        float tm0 = -1e30f, tm1 = -1e30f;
        #pragma unroll
        for (int nt = 0; nt < 8; nt++) {
            tm0 = fmaxf(tm0, fmaxf(sc[nt][0], sc[nt][1]));
            tm1 = fmaxf(tm1, fmaxf(sc[nt][2], sc[nt][3]));
        }
        tm0 = fmaxf(tm0, __shfl_xor_sync(0xffffffffu, tm0, 1));
        tm0 = fmaxf(tm0, __shfl_xor_sync(0xffffffffu, tm0, 2));
        tm1 = fmaxf(tm1, __shfl_xor_sync(0xffffffffu, tm1, 1));
        tm1 = fmaxf(tm1, __shfl_xor_sync(0xffffffffu, tm1, 2));

        const float nm0 = fmaxf(m0v, tm0), nm1 = fmaxf(m1v, tm1);
        const float es0 = ex2f(m0v - nm0), es1 = ex2f(m1v - nm1);
        m0v = nm0; m1v = nm1;

        // rescale accumulator
        #pragma unroll
        for (int d = 0; d < 8; d++) {
            ao[d][0] *= es0; ao[d][1] *= es0;
            ao[d][2] *= es1; ao[d][3] *= es1;
        }

        // O += P V with exp fused per-kb2 (only 4 packed P regs live at once);
        // row sums via ones-MMA (exact fp32 cross-quad sum of the fp16 P used).
        float su[4] = {0.f, 0.f, 0.f, 0.f};
        #pragma unroll
        for (int kb2 = 0; kb2 < 4; kb2++) {
            uint32_t pa[4];
            pa[0] = h2ex2(pkh2(sc[2*kb2][0]     - nm0, sc[2*kb2][1]     - nm0));
            pa[1] = h2ex2(pkh2(sc[2*kb2][2]     - nm1, sc[2*kb2][3]     - nm1));
            pa[2] = h2ex2(pkh2(sc[2*kb2 + 1][0] - nm0, sc[2*kb2 + 1][1] - nm0));
            pa[3] = h2ex2(pkh2(sc[2*kb2 + 1][2] - nm1, sc[2*kb2 + 1][3] - nm1));
            mma16816(su, pa, ONESH2, ONESH2);
            #pragma unroll
            for (int dp = 0; dp < 4; dp++) {
                uint32_t vf[4];
                ldsm4t(vf, uV[s] + (kb2*16 + lm) * 144 + dp*32 + lh16);
                mma16816(ao[2*dp],     pa, vf[0], vf[1]);
                mma16816(ao[2*dp + 1], pa, vf[2], vf[3]);
            }
        }
        l0 = l0 * es0 + su[0];
        l1 = l1 * es1 + su[2];
    }

    const float inv0 = 1.f / l0, inv1 = 1.f / l1;
    const int r0 = qt * 128 + wid * 16 + g;
    const size_t mrow0 = (size_t)(b * Tn + r0) * Dn;
    const size_t mrow1 = (size_t)(b * Tn + r0 + 8) * Dn;
    #pragma unroll
    for (int dt = 0; dt < 8; dt++) {
        const int c = h * 64 + dt * 8 + 2 * t;
        *(uint32_t*)(O + mrow0 + c) = pkh2(ao[dt][0] * inv0, ao[dt][1] * inv0);
        *(uint32_t*)(O + mrow1 + c) = pkh2(ao[dt][2] * inv1, ao[dt][3] * inv1);
    }
}

// ---------------------------------------------------------------------------
extern "C" void kernel_launch(void* const* d_in, const int* in_sizes, int n_in,
                              void* d_out, int out_size)
{
    (void)in_sizes; (void)n_in; (void)out_size;
    const float* x  = (const float*)d_in[0];
    const float* Wq = (const float*)d_in[1];
    const float* bq = (const float*)d_in[2];
    const float* Wk = (const float*)d_in[3];
    const float* bk = (const float*)d_in[4];
    const float* Wv = (const float*)d_in[5];
    const float* bv = (const float*)d_in[6];
    const float* Wo = (const float*)d_in[7];
    const float* bo = (const float*)d_in[8];
    float* out = (float*)d_out;

    __half *Qh, *Kh, *Vh, *attn;
    cudaGetSymbolAddress((void**)&Qh,   g_Qh);
    cudaGetSymbolAddress((void**)&Kh,   g_Kh);
    cudaGetSymbolAddress((void**)&Vh,   g_Vh);
    cudaGetSymbolAddress((void**)&attn, g_attn);

    cudaFuncSetAttribute(gemm_qkv_kernel, cudaFuncAttributeMaxDynamicSharedMemorySize, GSMEM);
    cudaFuncSetAttribute(gemm_o_kernel,   cudaFuncAttributeMaxDynamicSharedMemorySize, GSMEM);
    cudaFuncSetAttribute(attn_h_kernel,   cudaFuncAttributeMaxDynamicSharedMemorySize, ATTN_SMEM3);

    const int total = CVT_TOTAL + TBL_TOTAL;
    cvt_all_kernel<<<(total + 255) / 256, 256>>>(x, Wq, Wk, Wv, Wo);

    gemm_qkv_kernel<<<dim3(24, 32), 256, GSMEM>>>(bq, bk, bv);

    attn_h_kernel<<<dim3(Tn / 128, Bn * Hn), 256, ATTN_SMEM3>>>(Qh, Kh, Vh, attn);

    gemm_o_kernel<<<dim3(8, 32), 256, GSMEM>>>(bo, out);
}